// round 1
// baseline (speedup 1.0000x reference)
#include <cuda_runtime.h>
#include <cstdint>
#include <cstddef>

#define N_NODES 100000
#define B_BATCH 20000
#define K_NBR   10
#define F_DIM   256
#define H_DIM   128

#define ROWS 64     // embed rows per block in precompute
#define XP   260    // padded smem stride for X tile (multiple of 4)
#define HP   132    // padded smem stride for H tile (multiple of 4)

// Scratch: per-node precomputed [q(128) | k(128) | v(128)]
__device__ float g_table[(size_t)N_NODES * 384];

typedef unsigned long long ull;

__device__ __forceinline__ ull pack2(float lo, float hi) {
    ull r;
    asm("mov.b64 %0, {%1, %2};" : "=l"(r) : "f"(lo), "f"(hi));
    return r;
}
__device__ __forceinline__ void fma2(ull &d, ull a, ull b) {
    asm("fma.rn.f32x2 %0, %1, %2, %0;" : "+l"(d) : "l"(a), "l"(b));
}
__device__ __forceinline__ float2 unpack2(ull v) {
    float lo, hi;
    asm("mov.b64 {%0, %1}, %2;" : "=f"(lo), "=f"(hi) : "l"(v));
    return make_float2(lo, hi);
}

// ---------------------------------------------------------------------------
// Kernel 1: per-node QKV precompute.
//   table[r, p*128 + c] = ( tanh(embed[r,:] @ Wa_p) @ Wb_p )[c],  p = 0,1,2
// Tile: 64 rows x 128 cols, 128 threads, thread microtile 8x8 via f32x2 FMA.
// ---------------------------------------------------------------------------
__global__ void __launch_bounds__(128, 1) precompute_kernel(
    const float* __restrict__ embed,
    const float* __restrict__ W1a, const float* __restrict__ W1b,
    const float* __restrict__ W2a, const float* __restrict__ W2b,
    const float* __restrict__ W3a, const float* __restrict__ W3b)
{
    extern __shared__ float smem[];
    float* sX = smem;                    // [64][XP]   embed tile
    float* sW = sX + ROWS * XP;          // [64][128]  weight k-panel
    float* sH = sW + 64 * H_DIM;         // [64][HP]   hidden tile

    const int tid  = threadIdx.x;
    const int tx   = tid & 15;           // 16 col groups of 8
    const int ty   = tid >> 4;           // 8 row groups of 8
    const int row0 = ty * 8;
    const int col0 = tx * 8;
    const long brow = (long)blockIdx.x * ROWS;

    // Load X tile [64][256] (coalesced float4)
    for (int i = tid; i < ROWS * (F_DIM / 4); i += 128) {
        int r  = i >> 6;                 // 64 float4 per row
        int c4 = i & 63;
        long grow = brow + r;
        float4 v = make_float4(0.f, 0.f, 0.f, 0.f);
        if (grow < N_NODES) v = *(const float4*)(embed + grow * F_DIM + c4 * 4);
        *(float4*)(sX + r * XP + c4 * 4) = v;
    }

    const float* Wa[3] = {W1a, W2a, W3a};
    const float* Wb[3] = {W1b, W2b, W3b};

    for (int p = 0; p < 3; ++p) {
        ull acc[8][4];

        // ---------------- GEMM1: acc = X @ Wa[p]   (K = 256) ----------------
        #pragma unroll
        for (int r = 0; r < 8; r++)
            #pragma unroll
            for (int c = 0; c < 4; c++) acc[r][c] = 0ull;

        for (int kp = 0; kp < F_DIM; kp += 64) {
            __syncthreads();
            const float* wsrc = Wa[p] + (size_t)kp * H_DIM;
            for (int i = tid; i < 64 * (H_DIM / 4); i += 128) {
                int r = i >> 5, c4 = i & 31;
                *(float4*)(sW + r * H_DIM + c4 * 4) =
                    *(const float4*)(wsrc + r * H_DIM + c4 * 4);
            }
            __syncthreads();

            #pragma unroll 8
            for (int kk = 0; kk < 64; ++kk) {
                float xv[8];
                #pragma unroll
                for (int r = 0; r < 8; r++) xv[r] = sX[(row0 + r) * XP + kp + kk];
                float4 w0 = *(const float4*)(sW + kk * H_DIM + col0);
                float4 w1 = *(const float4*)(sW + kk * H_DIM + col0 + 4);
                ull wp0 = pack2(w0.x, w0.y), wp1 = pack2(w0.z, w0.w);
                ull wp2 = pack2(w1.x, w1.y), wp3 = pack2(w1.z, w1.w);
                #pragma unroll
                for (int r = 0; r < 8; r++) {
                    ull xr = pack2(xv[r], xv[r]);
                    fma2(acc[r][0], xr, wp0);
                    fma2(acc[r][1], xr, wp1);
                    fma2(acc[r][2], xr, wp2);
                    fma2(acc[r][3], xr, wp3);
                }
            }
        }

        // tanh epilogue -> sH
        __syncthreads();
        #pragma unroll
        for (int r = 0; r < 8; r++) {
            #pragma unroll
            for (int c = 0; c < 4; c++) {
                float2 v = unpack2(acc[r][c]);
                sH[(row0 + r) * HP + col0 + 2 * c]     = tanhf(v.x);
                sH[(row0 + r) * HP + col0 + 2 * c + 1] = tanhf(v.y);
            }
        }

        // ---------------- GEMM2: acc = H @ Wb[p]   (K = 128) ----------------
        #pragma unroll
        for (int r = 0; r < 8; r++)
            #pragma unroll
            for (int c = 0; c < 4; c++) acc[r][c] = 0ull;

        for (int kp = 0; kp < H_DIM; kp += 64) {
            __syncthreads();
            const float* wsrc = Wb[p] + (size_t)kp * H_DIM;
            for (int i = tid; i < 64 * (H_DIM / 4); i += 128) {
                int r = i >> 5, c4 = i & 31;
                *(float4*)(sW + r * H_DIM + c4 * 4) =
                    *(const float4*)(wsrc + r * H_DIM + c4 * 4);
            }
            __syncthreads();

            #pragma unroll 8
            for (int kk = 0; kk < 64; ++kk) {
                float xv[8];
                #pragma unroll
                for (int r = 0; r < 8; r++) xv[r] = sH[(row0 + r) * HP + kp + kk];
                float4 w0 = *(const float4*)(sW + kk * H_DIM + col0);
                float4 w1 = *(const float4*)(sW + kk * H_DIM + col0 + 4);
                ull wp0 = pack2(w0.x, w0.y), wp1 = pack2(w0.z, w0.w);
                ull wp2 = pack2(w1.x, w1.y), wp3 = pack2(w1.z, w1.w);
                #pragma unroll
                for (int r = 0; r < 8; r++) {
                    ull xr = pack2(xv[r], xv[r]);
                    fma2(acc[r][0], xr, wp0);
                    fma2(acc[r][1], xr, wp1);
                    fma2(acc[r][2], xr, wp2);
                    fma2(acc[r][3], xr, wp3);
                }
            }
        }

        // Write projection p to the table
        #pragma unroll
        for (int r = 0; r < 8; r++) {
            long grow = brow + row0 + r;
            if (grow < N_NODES) {
                float2 v0 = unpack2(acc[r][0]);
                float2 v1 = unpack2(acc[r][1]);
                float2 v2 = unpack2(acc[r][2]);
                float2 v3 = unpack2(acc[r][3]);
                float* dst = g_table + (size_t)grow * 384 + p * H_DIM + col0;
                *(float4*)dst       = make_float4(v0.x, v0.y, v1.x, v1.y);
                *(float4*)(dst + 4) = make_float4(v2.x, v2.y, v3.x, v3.y);
            }
        }
    }
}

// ---------------------------------------------------------------------------
// Kernel 2: gather + tiny attention. One warp per batch node, 2 batches/block.
//   S[i,j] = q_i . k_j ; att = softmax_j(S) ; out = (colsum_i att) @ V
// ---------------------------------------------------------------------------
__global__ void __launch_bounds__(64) attention_kernel(
    const int* __restrict__ neighbors, float* __restrict__ out)
{
    __shared__ float sD[2][K_NBR][384];  // gathered [q|k|v] rows per warp
    __shared__ float sS[2][128];         // scores(100) + rowsum(10) + colw(10)

    const int w    = threadIdx.x >> 5;
    const int lane = threadIdx.x & 31;
    const int b    = blockIdx.x * 2 + w;
    if (b >= B_BATCH) return;

    int mynode = 0;
    if (lane < K_NBR) mynode = neighbors[(size_t)b * K_NBR + lane];

    // Gather 10 x 384 floats (float4, lane-strided)
    for (int i = lane; i < K_NBR * 96; i += 32) {
        int j  = i / 96;
        int c4 = i - j * 96;
        int node = __shfl_sync(0xffffffffu, mynode, j);
        float4 v = *(const float4*)(g_table + (size_t)node * 384 + c4 * 4);
        *(float4*)(&sD[w][j][c4 * 4]) = v;
    }
    __syncwarp();

    // Score matrix: 100 dot products of length 128
    for (int pidx = lane; pidx < K_NBR * K_NBR; pidx += 32) {
        int i = pidx / K_NBR;
        int j = pidx - i * K_NBR;
        const float* qi = sD[w][i];
        const float* kj = sD[w][j] + 128;
        float s = 0.f;
        #pragma unroll
        for (int d = 0; d < 128; d += 4) {
            float4 a = *(const float4*)(qi + d);
            float4 c = *(const float4*)(kj + d);
            s = fmaf(a.x, c.x, s); s = fmaf(a.y, c.y, s);
            s = fmaf(a.z, c.z, s); s = fmaf(a.w, c.w, s);
        }
        sS[w][pidx] = s;
    }
    __syncwarp();

    // Row softmax numerators + row sums
    if (lane < K_NBR) {
        float m = -1e30f;
        #pragma unroll
        for (int j = 0; j < K_NBR; j++) m = fmaxf(m, sS[w][lane * K_NBR + j]);
        float sum = 0.f;
        #pragma unroll
        for (int j = 0; j < K_NBR; j++) {
            float e = __expf(sS[w][lane * K_NBR + j] - m);
            sS[w][lane * K_NBR + j] = e;
            sum += e;
        }
        sS[w][100 + lane] = sum;
    }
    __syncwarp();

    // Column weights: colw[j] = sum_i att[i][j]
    if (lane < K_NBR) {
        float cw = 0.f;
        #pragma unroll
        for (int i = 0; i < K_NBR; i++)
            cw += sS[w][i * K_NBR + lane] / sS[w][100 + i];
        sS[w][112 + lane] = cw;
    }
    __syncwarp();

    // out[b, :] = sum_j colw[j] * v_j   (each lane owns 4 dims)
    float4 o = make_float4(0.f, 0.f, 0.f, 0.f);
    const int d = lane * 4;
    #pragma unroll
    for (int j = 0; j < K_NBR; j++) {
        float cw = sS[w][112 + j];
        float4 v = *(const float4*)(&sD[w][j][256 + d]);
        o.x = fmaf(cw, v.x, o.x);
        o.y = fmaf(cw, v.y, o.y);
        o.z = fmaf(cw, v.z, o.z);
        o.w = fmaf(cw, v.w, o.w);
    }
    *(float4*)(out + (size_t)b * H_DIM + d) = o;
}

// ---------------------------------------------------------------------------
extern "C" void kernel_launch(void* const* d_in, const int* in_sizes, int n_in,
                              void* d_out, int out_size) {
    const int*   neighbors = (const int*)d_in[0];
    const float* embed     = (const float*)d_in[1];
    const float* W1a       = (const float*)d_in[2];
    const float* W1b       = (const float*)d_in[3];
    const float* W2a       = (const float*)d_in[4];
    const float* W2b       = (const float*)d_in[5];
    const float* W3a       = (const float*)d_in[6];
    const float* W3b       = (const float*)d_in[7];
    float* out = (float*)d_out;

    const size_t smem_bytes =
        (size_t)(ROWS * XP + 64 * H_DIM + ROWS * HP) * sizeof(float); // 133120
    cudaFuncSetAttribute(precompute_kernel,
                         cudaFuncAttributeMaxDynamicSharedMemorySize,
                         (int)smem_bytes);

    const int grid1 = (N_NODES + ROWS - 1) / ROWS;
    precompute_kernel<<<grid1, 128, smem_bytes>>>(embed, W1a, W1b, W2a, W2b,
                                                  W3a, W3b);

    const int grid2 = (B_BATCH + 1) / 2;
    attention_kernel<<<grid2, 64>>>(neighbors, out);
}

// round 3
// speedup vs baseline: 3.9754x; 3.9754x over previous
#include <cuda_runtime.h>
#include <cuda_bf16.h>
#include <cstdint>
#include <cstddef>

#define N_NODES 100000
#define B_BATCH 20000
#define K_NBR   10
#define F_DIM   256
#define H_DIM   128

// ---------------------------------------------------------------------------
// Device scratch
// ---------------------------------------------------------------------------
__device__ float g_table[(size_t)N_NODES * 384];      // [q|k|v] per node
// Prepacked B fragments (mma.m16n8k16 register layout), hi/lo split terms.
// Ba: [p][kstep(16)][term(2)][ntile(16)][lane(32)]  (K=256 GEMM1)
// Bb: [p][kstep(8) ][term(2)][ntile(16)][lane(32)]  (K=128 GEMM2)
__device__ uint2 g_Ba[3 * 16 * 2 * 16 * 32];
__device__ uint2 g_Bb[3 *  8 * 2 * 16 * 32];

// ---------------------------------------------------------------------------
// Helpers
// ---------------------------------------------------------------------------
__device__ __forceinline__ uint32_t smem_u32(const void* p) {
    uint32_t a;
    asm("{ .reg .u64 t; cvta.to.shared.u64 t, %1; cvt.u32.u64 %0, t; }"
        : "=r"(a) : "l"(p));
    return a;
}
// pack two floats as bf16x2: 'lo' -> lower 16 bits, 'hi' -> upper 16 bits
__device__ __forceinline__ uint32_t pack_bf16x2(float lo, float hi) {
    uint32_t r;
    asm("cvt.rn.bf16x2.f32 %0, %1, %2;" : "=r"(r) : "f"(hi), "f"(lo));
    return r;
}
__device__ __forceinline__ float bf16_round(float x) {
    return __bfloat162float(__float2bfloat16_rn(x));
}
__device__ __forceinline__ float tanh_fast(float x) {
    float e = __expf(2.f * x);
    return 1.f - __fdividef(2.f, e + 1.f);
}
__device__ __forceinline__ void ldm4(uint32_t* r, uint32_t addr) {
    asm volatile("ldmatrix.sync.aligned.m8n8.x4.shared.b16 {%0,%1,%2,%3}, [%4];"
                 : "=r"(r[0]), "=r"(r[1]), "=r"(r[2]), "=r"(r[3]) : "r"(addr));
}
__device__ __forceinline__ void mma16816(float* d, const uint32_t* a,
                                         uint32_t b0, uint32_t b1) {
    asm volatile(
        "mma.sync.aligned.m16n8k16.row.col.f32.bf16.bf16.f32 "
        "{%0,%1,%2,%3}, {%4,%5,%6,%7}, {%8,%9}, {%0,%1,%2,%3};"
        : "+f"(d[0]), "+f"(d[1]), "+f"(d[2]), "+f"(d[3])
        : "r"(a[0]), "r"(a[1]), "r"(a[2]), "r"(a[3]), "r"(b0), "r"(b1));
}

// ---------------------------------------------------------------------------
// Kernel 0: prepack weights into mma B-fragment register layout (hi/lo bf16).
// Fragment element map (m16n8k16 B, col-major k16xn8):
//   reg.x: k = kstep*16 + (lane%4)*2 + {0,1}, n = ntile*8 + lane/4
//   reg.y: k = ... + 8 + {0,1}
// ---------------------------------------------------------------------------
__global__ void prep_weights_kernel(
    const float* __restrict__ W1a, const float* __restrict__ W1b,
    const float* __restrict__ W2a, const float* __restrict__ W2b,
    const float* __restrict__ W3a, const float* __restrict__ W3b)
{
    const float* Wa[3] = {W1a, W2a, W3a};
    const float* Wb[3] = {W1b, W2b, W3b};
    int i = blockIdx.x * blockDim.x + threadIdx.x;   // 36864 threads total
    const float* W;
    uint2* dst_hi;
    uint2* dst_lo;
    int lane, nt, ks;
    if (i < 24576) {                                 // Ba: 3*16*16*32
        lane = i & 31; nt = (i >> 5) & 15; ks = (i >> 9) & 15;
        int p = i >> 13;
        W = Wa[p];
        size_t base = ((size_t)(p * 16 + ks) * 2) * 512 + nt * 32 + lane;
        dst_hi = g_Ba + base;
        dst_lo = g_Ba + base + 512;
    } else {
        int ib = i - 24576;                          // Bb: 3*8*16*32
        lane = ib & 31; nt = (ib >> 5) & 15; ks = (ib >> 9) & 7;
        int p = ib >> 12;
        W = Wb[p];
        size_t base = ((size_t)(p * 8 + ks) * 2) * 512 + nt * 32 + lane;
        dst_hi = g_Bb + base;
        dst_lo = g_Bb + base + 512;
    }
    int k = ks * 16 + (lane & 3) * 2;
    int n = nt * 8 + (lane >> 2);
    float w00 = W[(size_t)k * H_DIM + n];
    float w01 = W[(size_t)(k + 1) * H_DIM + n];
    float w10 = W[(size_t)(k + 8) * H_DIM + n];
    float w11 = W[(size_t)(k + 9) * H_DIM + n];
    float h00 = bf16_round(w00), h01 = bf16_round(w01);
    float h10 = bf16_round(w10), h11 = bf16_round(w11);
    uint2 hi, lo;
    hi.x = pack_bf16x2(h00, h01);
    hi.y = pack_bf16x2(h10, h11);
    lo.x = pack_bf16x2(w00 - h00, w01 - h01);
    lo.y = pack_bf16x2(w10 - h10, w11 - h11);
    *dst_hi = hi;
    *dst_lo = lo;
}

// ---------------------------------------------------------------------------
// Kernel 1: HMMA precompute. CTA = 128 rows x 128 cols, 8 warps (4m x 2n),
// warp tile 32x64. Split-3 bf16: D = Ah*Bh + Ah*Bl + Al*Bh (fp32 accum).
// ---------------------------------------------------------------------------
#define XSTR 264                         // X smem row stride (bf16 elems)
#define HSTR 136                         // H smem row stride
#define XHI_OFF 0u
#define XLO_OFF 67584u                   // 128*264*2
#define HHI_OFF 135168u
#define HLO_OFF 169984u                  // +128*136*2
#define PC_SMEM 204800u

__global__ void __launch_bounds__(256, 1) precompute_mma_kernel(
    const float* __restrict__ embed)
{
    extern __shared__ unsigned char smem[];
    const uint32_t sbase = smem_u32(smem);
    const int tid  = threadIdx.x;
    const int wid  = tid >> 5;
    const int lane = tid & 31;
    const int wm   = wid & 3;            // m-group: rows wm*32..+31
    const int wn   = wid >> 2;           // n-group: cols wn*64..+63
    const long brow = (long)blockIdx.x * 128;

    // ldmatrix per-lane address offsets (bytes): row = lane&15, colofs = (lane>>4)*8
    const uint32_t loffX = (uint32_t)((lane & 15) * XSTR + (lane >> 4) * 8) * 2;
    const uint32_t loffH = (uint32_t)((lane & 15) * HSTR + (lane >> 4) * 8) * 2;

    // ---- Load X tile [128][256] fp32 -> bf16 hi/lo smem ----
    for (int i = tid; i < 128 * 64; i += 256) {
        int r  = i >> 6;
        int c4 = i & 63;
        long grow = brow + r;
        float4 v = make_float4(0.f, 0.f, 0.f, 0.f);
        if (grow < N_NODES) v = *(const float4*)(embed + grow * F_DIM + c4 * 4);
        float h0 = bf16_round(v.x), h1 = bf16_round(v.y);
        float h2 = bf16_round(v.z), h3 = bf16_round(v.w);
        uint32_t off = ((uint32_t)r * XSTR + c4 * 4) * 2;
        *(uint32_t*)(smem + XHI_OFF + off)     = pack_bf16x2(h0, h1);
        *(uint32_t*)(smem + XHI_OFF + off + 4) = pack_bf16x2(h2, h3);
        *(uint32_t*)(smem + XLO_OFF + off)     = pack_bf16x2(v.x - h0, v.y - h1);
        *(uint32_t*)(smem + XLO_OFF + off + 4) = pack_bf16x2(v.z - h2, v.w - h3);
    }
    __syncthreads();

    const int rbase = (lane >> 2);       // accumulator row within m16 tile
    const int cbase = (lane & 3) * 2;    // accumulator col within n8 tile

    for (int p = 0; p < 3; p++) {
        float acc[2][8][4];
        #pragma unroll
        for (int mt = 0; mt < 2; mt++)
            #pragma unroll
            for (int nt = 0; nt < 8; nt++)
                #pragma unroll
                for (int c = 0; c < 4; c++) acc[mt][nt][c] = 0.f;

        // ================= GEMM1: X[128,256] @ Wa -> 128x128 =================
        for (int ks = 0; ks < 16; ks++) {
            uint32_t ah[2][4], al[2][4];
            uint32_t kb = (uint32_t)ks * 32;  // ks*16 elems * 2B
            #pragma unroll
            for (int mt = 0; mt < 2; mt++) {
                uint32_t ro = (uint32_t)(wm * 32 + mt * 16) * XSTR * 2;
                ldm4(ah[mt], sbase + XHI_OFF + ro + kb + loffX);
                ldm4(al[mt], sbase + XLO_OFF + ro + kb + loffX);
            }
            const uint2* pb = g_Ba + ((size_t)(p * 16 + ks) * 2) * 512
                              + wn * 256 + lane;
            uint2 bh[8], bl[8];
            #pragma unroll
            for (int j = 0; j < 8; j++) { bh[j] = pb[j * 32]; bl[j] = pb[512 + j * 32]; }
            #pragma unroll
            for (int j = 0; j < 8; j++) {
                #pragma unroll
                for (int mt = 0; mt < 2; mt++) {
                    mma16816(acc[mt][j], ah[mt], bh[j].x, bh[j].y);
                    mma16816(acc[mt][j], ah[mt], bl[j].x, bl[j].y);
                    mma16816(acc[mt][j], al[mt], bh[j].x, bh[j].y);
                }
            }
        }

        // ---- Epilogue 1: tanh -> H smem (bf16 hi/lo) ----
        #pragma unroll
        for (int mt = 0; mt < 2; mt++) {
            #pragma unroll
            for (int nt = 0; nt < 8; nt++) {
                int col = wn * 64 + nt * 8 + cbase;
                int r0  = wm * 32 + mt * 16 + rbase;
                float t0 = tanh_fast(acc[mt][nt][0]);
                float t1 = tanh_fast(acc[mt][nt][1]);
                float t2 = tanh_fast(acc[mt][nt][2]);
                float t3 = tanh_fast(acc[mt][nt][3]);
                float h0 = bf16_round(t0), h1 = bf16_round(t1);
                float h2 = bf16_round(t2), h3 = bf16_round(t3);
                uint32_t o0 = ((uint32_t)r0 * HSTR + col) * 2;
                uint32_t o1 = ((uint32_t)(r0 + 8) * HSTR + col) * 2;
                *(uint32_t*)(smem + HHI_OFF + o0) = pack_bf16x2(h0, h1);
                *(uint32_t*)(smem + HHI_OFF + o1) = pack_bf16x2(h2, h3);
                *(uint32_t*)(smem + HLO_OFF + o0) = pack_bf16x2(t0 - h0, t1 - h1);
                *(uint32_t*)(smem + HLO_OFF + o1) = pack_bf16x2(t2 - h2, t3 - h3);
            }
        }
        __syncthreads();

        // ================= GEMM2: H[128,128] @ Wb -> 128x128 =================
        #pragma unroll
        for (int mt = 0; mt < 2; mt++)
            #pragma unroll
            for (int nt = 0; nt < 8; nt++)
                #pragma unroll
                for (int c = 0; c < 4; c++) acc[mt][nt][c] = 0.f;

        for (int ks = 0; ks < 8; ks++) {
            uint32_t ah[2][4], al[2][4];
            uint32_t kb = (uint32_t)ks * 32;
            #pragma unroll
            for (int mt = 0; mt < 2; mt++) {
                uint32_t ro = (uint32_t)(wm * 32 + mt * 16) * HSTR * 2;
                ldm4(ah[mt], sbase + HHI_OFF + ro + kb + loffH);
                ldm4(al[mt], sbase + HLO_OFF + ro + kb + loffH);
            }
            const uint2* pb = g_Bb + ((size_t)(p * 8 + ks) * 2) * 512
                              + wn * 256 + lane;
            uint2 bh[8], bl[8];
            #pragma unroll
            for (int j = 0; j < 8; j++) { bh[j] = pb[j * 32]; bl[j] = pb[512 + j * 32]; }
            #pragma unroll
            for (int j = 0; j < 8; j++) {
                #pragma unroll
                for (int mt = 0; mt < 2; mt++) {
                    mma16816(acc[mt][j], ah[mt], bh[j].x, bh[j].y);
                    mma16816(acc[mt][j], ah[mt], bl[j].x, bl[j].y);
                    mma16816(acc[mt][j], al[mt], bh[j].x, bh[j].y);
                }
            }
        }

        // ---- Epilogue 2: write to g_table ----
        #pragma unroll
        for (int mt = 0; mt < 2; mt++) {
            #pragma unroll
            for (int nt = 0; nt < 8; nt++) {
                int col = wn * 64 + nt * 8 + cbase;
                long r0 = brow + wm * 32 + mt * 16 + rbase;
                if (r0 < N_NODES) {
                    float2 v = make_float2(acc[mt][nt][0], acc[mt][nt][1]);
                    *(float2*)(g_table + r0 * 384 + p * H_DIM + col) = v;
                }
                if (r0 + 8 < N_NODES) {
                    float2 v = make_float2(acc[mt][nt][2], acc[mt][nt][3]);
                    *(float2*)(g_table + (r0 + 8) * 384 + p * H_DIM + col) = v;
                }
            }
        }
        __syncthreads();   // protect H smem before next projection rewrites it
    }
}

// ---------------------------------------------------------------------------
// Kernel 2: gather + tiny attention. One 128-thread block per batch node.
// ---------------------------------------------------------------------------
#define DSTR 396
__global__ void __launch_bounds__(128) attention_kernel(
    const int* __restrict__ neighbors, float* __restrict__ out)
{
    __shared__ float sD[K_NBR][DSTR];    // gathered [q|k|v] rows
    __shared__ float sS[100];            // exp(scores)
    __shared__ float sR[K_NBR];          // row sums
    __shared__ float sC[K_NBR];          // column weights
    __shared__ int   snode[K_NBR];

    const int b   = blockIdx.x;
    const int tid = threadIdx.x;

    if (tid < K_NBR) snode[tid] = neighbors[(size_t)b * K_NBR + tid];
    __syncthreads();

    for (int i = tid; i < K_NBR * 96; i += 128) {
        int j  = i / 96;
        int c4 = i - j * 96;
        float4 v = *(const float4*)(g_table + (size_t)snode[j] * 384 + c4 * 4);
        *(float4*)(&sD[j][c4 * 4]) = v;
    }
    __syncthreads();

    if (tid < 100) {
        int i = tid / K_NBR;
        int j = tid - i * K_NBR;
        const float* qi = sD[i];
        const float* kj = sD[j] + 128;
        float s = 0.f;
        #pragma unroll
        for (int d = 0; d < 128; d += 4) {
            float4 a = *(const float4*)(qi + d);
            float4 c = *(const float4*)(kj + d);
            s = fmaf(a.x, c.x, s); s = fmaf(a.y, c.y, s);
            s = fmaf(a.z, c.z, s); s = fmaf(a.w, c.w, s);
        }
        sS[tid] = s;
    }
    __syncthreads();

    if (tid < K_NBR) {
        float m = -1e30f;
        #pragma unroll
        for (int j = 0; j < K_NBR; j++) m = fmaxf(m, sS[tid * K_NBR + j]);
        float sum = 0.f;
        #pragma unroll
        for (int j = 0; j < K_NBR; j++) {
            float e = __expf(sS[tid * K_NBR + j] - m);
            sS[tid * K_NBR + j] = e;
            sum += e;
        }
        sR[tid] = sum;
    }
    __syncthreads();

    if (tid < K_NBR) {
        float cw = 0.f;
        #pragma unroll
        for (int i = 0; i < K_NBR; i++)
            cw += sS[i * K_NBR + tid] / sR[i];
        sC[tid] = cw;
    }
    __syncthreads();

    float o = 0.f;
    #pragma unroll
    for (int j = 0; j < K_NBR; j++)
        o = fmaf(sC[j], sD[j][256 + tid], o);
    out[(size_t)b * H_DIM + tid] = o;
}

// ---------------------------------------------------------------------------
extern "C" void kernel_launch(void* const* d_in, const int* in_sizes, int n_in,
                              void* d_out, int out_size) {
    const int*   neighbors = (const int*)d_in[0];
    const float* embed     = (const float*)d_in[1];
    const float* W1a       = (const float*)d_in[2];
    const float* W1b       = (const float*)d_in[3];
    const float* W2a       = (const float*)d_in[4];
    const float* W2b       = (const float*)d_in[5];
    const float* W3a       = (const float*)d_in[6];
    const float* W3b       = (const float*)d_in[7];
    float* out = (float*)d_out;

    prep_weights_kernel<<<144, 256>>>(W1a, W1b, W2a, W2b, W3a, W3b);

    cudaFuncSetAttribute(precompute_mma_kernel,
                         cudaFuncAttributeMaxDynamicSharedMemorySize,
                         (int)PC_SMEM);
    const int grid1 = (N_NODES + 127) / 128;   // 782
    precompute_mma_kernel<<<grid1, 256, PC_SMEM>>>(embed);

    attention_kernel<<<B_BATCH, 128>>>(neighbors, out);
}

// round 4
// speedup vs baseline: 5.0962x; 1.2819x over previous
#include <cuda_runtime.h>
#include <cuda_fp16.h>
#include <cstdint>
#include <cstddef>

#define N_NODES 100000
#define B_BATCH 20000
#define K_NBR   10
#define F_DIM   256
#define H_DIM   128

// ---------------------------------------------------------------------------
// Device scratch
// ---------------------------------------------------------------------------
__device__ float g_table[(size_t)N_NODES * 384];      // [q|k|v] per node
// Prepacked fp16 B fragments (mma.m16n8k16 register layout).
// Ba: [p][kstep(16)][ntile(16)][lane(32)]  (K=256 GEMM1)
// Bb: [p][kstep(8) ][ntile(16)][lane(32)]  (K=128 GEMM2)
__device__ uint2 g_Ba[3 * 16 * 16 * 32];
__device__ uint2 g_Bb[3 *  8 * 16 * 32];

// ---------------------------------------------------------------------------
// Helpers
// ---------------------------------------------------------------------------
__device__ __forceinline__ uint32_t smem_u32(const void* p) {
    uint32_t a;
    asm("{ .reg .u64 t; cvta.to.shared.u64 t, %1; cvt.u32.u64 %0, t; }"
        : "=r"(a) : "l"(p));
    return a;
}
// pack two floats to f16x2: 'a' -> low 16 bits, 'b' -> high 16 bits
__device__ __forceinline__ uint32_t pack_f16x2(float a, float b) {
    half2 h = __floats2half2_rn(a, b);
    return *(uint32_t*)&h;
}
__device__ __forceinline__ float f16_round(float x) {
    return __half2float(__float2half_rn(x));
}
__device__ __forceinline__ float tanh_fast(float x) {
    float e = __expf(2.f * x);
    return 1.f - __fdividef(2.f, e + 1.f);
}
__device__ __forceinline__ void ldm4(uint32_t* r, uint32_t addr) {
    asm volatile("ldmatrix.sync.aligned.m8n8.x4.shared.b16 {%0,%1,%2,%3}, [%4];"
                 : "=r"(r[0]), "=r"(r[1]), "=r"(r[2]), "=r"(r[3]) : "r"(addr));
}
__device__ __forceinline__ void mma16816(float* d, const uint32_t* a,
                                         uint32_t b0, uint32_t b1) {
    asm volatile(
        "mma.sync.aligned.m16n8k16.row.col.f32.f16.f16.f32 "
        "{%0,%1,%2,%3}, {%4,%5,%6,%7}, {%8,%9}, {%0,%1,%2,%3};"
        : "+f"(d[0]), "+f"(d[1]), "+f"(d[2]), "+f"(d[3])
        : "r"(a[0]), "r"(a[1]), "r"(a[2]), "r"(a[3]), "r"(b0), "r"(b1));
}

// ---------------------------------------------------------------------------
// Kernel 0: prepack weights into mma B-fragment register layout (fp16).
//   reg.x: k = kstep*16 + (lane%4)*2 + {0,1}, n = ntile*8 + lane/4
//   reg.y: k = ... + 8 + {0,1}
// ---------------------------------------------------------------------------
__global__ void prep_weights_kernel(
    const float* __restrict__ W1a, const float* __restrict__ W1b,
    const float* __restrict__ W2a, const float* __restrict__ W2b,
    const float* __restrict__ W3a, const float* __restrict__ W3b)
{
    const float* Wa[3] = {W1a, W2a, W3a};
    const float* Wb[3] = {W1b, W2b, W3b};
    int i = blockIdx.x * blockDim.x + threadIdx.x;   // 36864 threads total
    const float* W;
    uint2* dst;
    int lane, nt, ks;
    if (i < 24576) {                                 // Ba: 3*16*16*32
        lane = i & 31; nt = (i >> 5) & 15; ks = (i >> 9) & 15;
        int p = i >> 13;
        W = Wa[p];
        dst = g_Ba + (size_t)(p * 16 + ks) * 512 + nt * 32 + lane;
    } else {                                         // Bb: 3*8*16*32
        int ib = i - 24576;
        lane = ib & 31; nt = (ib >> 5) & 15; ks = (ib >> 9) & 7;
        int p = ib >> 12;
        W = Wb[p];
        dst = g_Bb + (size_t)(p * 8 + ks) * 512 + nt * 32 + lane;
    }
    int k = ks * 16 + (lane & 3) * 2;
    int n = nt * 8 + (lane >> 2);
    float w00 = W[(size_t)k * H_DIM + n];
    float w01 = W[(size_t)(k + 1) * H_DIM + n];
    float w10 = W[(size_t)(k + 8) * H_DIM + n];
    float w11 = W[(size_t)(k + 9) * H_DIM + n];
    uint2 hi;
    hi.x = pack_f16x2(w00, w01);
    hi.y = pack_f16x2(w10, w11);
    *dst = hi;
}

// ---------------------------------------------------------------------------
// Kernel 1: HMMA precompute. CTA = 128 rows x 128 cols, 8 warps (4m x 2n),
// warp tile 32x64. fp16 split-2: D = (Ah + Al) * B16  (fp32 accum).
// ---------------------------------------------------------------------------
#define XSTR 264                         // X smem row stride (fp16 elems)
#define HSTR 136                         // H smem row stride
#define XHI_OFF 0u
#define XLO_OFF 67584u                   // 128*264*2
#define HHI_OFF 135168u
#define HLO_OFF 169984u                  // +128*136*2
#define PC_SMEM 204800u

__global__ void __launch_bounds__(256, 1) precompute_mma_kernel(
    const float* __restrict__ embed)
{
    extern __shared__ unsigned char smem[];
    const uint32_t sbase = smem_u32(smem);
    const int tid  = threadIdx.x;
    const int wid  = tid >> 5;
    const int lane = tid & 31;
    const int wm   = wid & 3;            // m-group: rows wm*32..+31
    const int wn   = wid >> 2;           // n-group: cols wn*64..+63
    const long brow = (long)blockIdx.x * 128;

    const uint32_t loffX = (uint32_t)((lane & 15) * XSTR + (lane >> 4) * 8) * 2;
    const uint32_t loffH = (uint32_t)((lane & 15) * HSTR + (lane >> 4) * 8) * 2;

    // ---- Load X tile [128][256] fp32 -> fp16 hi/lo smem ----
    for (int i = tid; i < 128 * 64; i += 256) {
        int r  = i >> 6;
        int c4 = i & 63;
        long grow = brow + r;
        float4 v = make_float4(0.f, 0.f, 0.f, 0.f);
        if (grow < N_NODES) v = *(const float4*)(embed + grow * F_DIM + c4 * 4);
        float h0 = f16_round(v.x), h1 = f16_round(v.y);
        float h2 = f16_round(v.z), h3 = f16_round(v.w);
        uint32_t off = ((uint32_t)r * XSTR + c4 * 4) * 2;
        *(uint32_t*)(smem + XHI_OFF + off)     = pack_f16x2(h0, h1);
        *(uint32_t*)(smem + XHI_OFF + off + 4) = pack_f16x2(h2, h3);
        *(uint32_t*)(smem + XLO_OFF + off)     = pack_f16x2(v.x - h0, v.y - h1);
        *(uint32_t*)(smem + XLO_OFF + off + 4) = pack_f16x2(v.z - h2, v.w - h3);
    }
    __syncthreads();

    const int rbase = (lane >> 2);
    const int cbase = (lane & 3) * 2;

    for (int p = 0; p < 3; p++) {
        float acc[2][8][4];
        #pragma unroll
        for (int mt = 0; mt < 2; mt++)
            #pragma unroll
            for (int nt = 0; nt < 8; nt++)
                #pragma unroll
                for (int c = 0; c < 4; c++) acc[mt][nt][c] = 0.f;

        // ================= GEMM1: X[128,256] @ Wa -> 128x128 =================
        {
            const uint2* pb = g_Ba + (size_t)(p * 16) * 512 + wn * 256 + lane;
            uint2 bh[8], bn[8];
            #pragma unroll
            for (int j = 0; j < 8; j++) bh[j] = pb[j * 32];
            for (int ks = 0; ks < 16; ks++) {
                const uint2* np = pb + (ks + 1) * 512;
                #pragma unroll
                for (int j = 0; j < 8; j++)
                    bn[j] = (ks < 15) ? np[j * 32] : make_uint2(0u, 0u);
                uint32_t ah[2][4], al[2][4];
                uint32_t kb = (uint32_t)ks * 32;
                #pragma unroll
                for (int mt = 0; mt < 2; mt++) {
                    uint32_t ro = (uint32_t)(wm * 32 + mt * 16) * XSTR * 2;
                    ldm4(ah[mt], sbase + XHI_OFF + ro + kb + loffX);
                    ldm4(al[mt], sbase + XLO_OFF + ro + kb + loffX);
                }
                #pragma unroll
                for (int j = 0; j < 8; j++) {
                    #pragma unroll
                    for (int mt = 0; mt < 2; mt++) {
                        mma16816(acc[mt][j], ah[mt], bh[j].x, bh[j].y);
                        mma16816(acc[mt][j], al[mt], bh[j].x, bh[j].y);
                    }
                }
                #pragma unroll
                for (int j = 0; j < 8; j++) bh[j] = bn[j];
            }
        }

        // ---- Epilogue 1: tanh -> H smem (fp16 hi/lo) ----
        #pragma unroll
        for (int mt = 0; mt < 2; mt++) {
            #pragma unroll
            for (int nt = 0; nt < 8; nt++) {
                int col = wn * 64 + nt * 8 + cbase;
                int r0  = wm * 32 + mt * 16 + rbase;
                float t0 = tanh_fast(acc[mt][nt][0]);
                float t1 = tanh_fast(acc[mt][nt][1]);
                float t2 = tanh_fast(acc[mt][nt][2]);
                float t3 = tanh_fast(acc[mt][nt][3]);
                float h0 = f16_round(t0), h1 = f16_round(t1);
                float h2 = f16_round(t2), h3 = f16_round(t3);
                uint32_t o0 = ((uint32_t)r0 * HSTR + col) * 2;
                uint32_t o1 = ((uint32_t)(r0 + 8) * HSTR + col) * 2;
                *(uint32_t*)(smem + HHI_OFF + o0) = pack_f16x2(h0, h1);
                *(uint32_t*)(smem + HHI_OFF + o1) = pack_f16x2(h2, h3);
                *(uint32_t*)(smem + HLO_OFF + o0) = pack_f16x2(t0 - h0, t1 - h1);
                *(uint32_t*)(smem + HLO_OFF + o1) = pack_f16x2(t2 - h2, t3 - h3);
            }
        }
        __syncthreads();

        // ================= GEMM2: H[128,128] @ Wb -> 128x128 =================
        #pragma unroll
        for (int mt = 0; mt < 2; mt++)
            #pragma unroll
            for (int nt = 0; nt < 8; nt++)
                #pragma unroll
                for (int c = 0; c < 4; c++) acc[mt][nt][c] = 0.f;

        {
            const uint2* pb = g_Bb + (size_t)(p * 8) * 512 + wn * 256 + lane;
            uint2 bh[8], bn[8];
            #pragma unroll
            for (int j = 0; j < 8; j++) bh[j] = pb[j * 32];
            for (int ks = 0; ks < 8; ks++) {
                const uint2* np = pb + (ks + 1) * 512;
                #pragma unroll
                for (int j = 0; j < 8; j++)
                    bn[j] = (ks < 7) ? np[j * 32] : make_uint2(0u, 0u);
                uint32_t ah[2][4], al[2][4];
                uint32_t kb = (uint32_t)ks * 32;
                #pragma unroll
                for (int mt = 0; mt < 2; mt++) {
                    uint32_t ro = (uint32_t)(wm * 32 + mt * 16) * HSTR * 2;
                    ldm4(ah[mt], sbase + HHI_OFF + ro + kb + loffH);
                    ldm4(al[mt], sbase + HLO_OFF + ro + kb + loffH);
                }
                #pragma unroll
                for (int j = 0; j < 8; j++) {
                    #pragma unroll
                    for (int mt = 0; mt < 2; mt++) {
                        mma16816(acc[mt][j], ah[mt], bh[j].x, bh[j].y);
                        mma16816(acc[mt][j], al[mt], bh[j].x, bh[j].y);
                    }
                }
                #pragma unroll
                for (int j = 0; j < 8; j++) bh[j] = bn[j];
            }
        }

        // ---- Epilogue 2: write to g_table ----
        #pragma unroll
        for (int mt = 0; mt < 2; mt++) {
            #pragma unroll
            for (int nt = 0; nt < 8; nt++) {
                int col = wn * 64 + nt * 8 + cbase;
                long r0 = brow + wm * 32 + mt * 16 + rbase;
                if (r0 < N_NODES) {
                    float2 v = make_float2(acc[mt][nt][0], acc[mt][nt][1]);
                    *(float2*)(g_table + r0 * 384 + p * H_DIM + col) = v;
                }
                if (r0 + 8 < N_NODES) {
                    float2 v = make_float2(acc[mt][nt][2], acc[mt][nt][3]);
                    *(float2*)(g_table + (r0 + 8) * 384 + p * H_DIM + col) = v;
                }
            }
        }
        __syncthreads();
    }
}

// ---------------------------------------------------------------------------
// Kernel 2: gather + tiny attention. 128 threads per batch node.
// Scores: warp G owns 25 (i,j) pairs; lane owns dims 4*lane..+3; k rows
// cached in registers; per-pair shfl_xor reduction (no big smem traffic).
// ---------------------------------------------------------------------------
#define DSTR 396

template<int G>
__device__ __forceinline__ void score_warp25(const float (*sD)[DSTR],
                                             float* sS, int lane) {
    float4 kv[K_NBR];
    #pragma unroll
    for (int j = 0; j < K_NBR; j++)
        kv[j] = *(const float4*)(&sD[j][128 + 4 * lane]);
    float4 qv = make_float4(0.f, 0.f, 0.f, 0.f);
    #pragma unroll
    for (int p = 0; p < 25; p++) {
        const int gp = G * 25 + p;
        const int i  = gp / K_NBR;
        const int j  = gp % K_NBR;
        if (p == 0 || (gp % K_NBR) == 0)
            qv = *(const float4*)(&sD[i][4 * lane]);
        float s = qv.x * kv[j].x;
        s = fmaf(qv.y, kv[j].y, s);
        s = fmaf(qv.z, kv[j].z, s);
        s = fmaf(qv.w, kv[j].w, s);
        s += __shfl_xor_sync(0xffffffffu, s, 16);
        s += __shfl_xor_sync(0xffffffffu, s, 8);
        s += __shfl_xor_sync(0xffffffffu, s, 4);
        s += __shfl_xor_sync(0xffffffffu, s, 2);
        s += __shfl_xor_sync(0xffffffffu, s, 1);
        if (lane == 0) sS[gp] = s;
    }
}

__global__ void __launch_bounds__(128) attention_kernel(
    const int* __restrict__ neighbors, float* __restrict__ out)
{
    __shared__ float sD[K_NBR][DSTR];    // gathered [q|k|v] rows
    __shared__ float sS[100];            // scores -> exp(scores)
    __shared__ float sR[K_NBR];          // row sums
    __shared__ float sC[K_NBR];          // column weights
    __shared__ int   snode[K_NBR];

    const int b    = blockIdx.x;
    const int tid  = threadIdx.x;
    const int lane = tid & 31;
    const int g    = tid >> 5;

    if (tid < K_NBR) snode[tid] = neighbors[(size_t)b * K_NBR + tid];
    __syncthreads();

    for (int i = tid; i < K_NBR * 96; i += 128) {
        int j  = i / 96;
        int c4 = i - j * 96;
        float4 v = *(const float4*)(g_table + (size_t)snode[j] * 384 + c4 * 4);
        *(float4*)(&sD[j][c4 * 4]) = v;
    }
    __syncthreads();

    switch (g) {
        case 0: score_warp25<0>(sD, sS, lane); break;
        case 1: score_warp25<1>(sD, sS, lane); break;
        case 2: score_warp25<2>(sD, sS, lane); break;
        default: score_warp25<3>(sD, sS, lane); break;
    }
    __syncthreads();

    if (tid < K_NBR) {
        float m = -1e30f;
        #pragma unroll
        for (int j = 0; j < K_NBR; j++) m = fmaxf(m, sS[tid * K_NBR + j]);
        float sum = 0.f;
        #pragma unroll
        for (int j = 0; j < K_NBR; j++) {
            float e = __expf(sS[tid * K_NBR + j] - m);
            sS[tid * K_NBR + j] = e;
            sum += e;
        }
        sR[tid] = sum;
    }
    __syncthreads();

    if (tid < K_NBR) {
        float cw = 0.f;
        #pragma unroll
        for (int i = 0; i < K_NBR; i++)
            cw += sS[i * K_NBR + tid] / sR[i];
        sC[tid] = cw;
    }
    __syncthreads();

    float o = 0.f;
    #pragma unroll
    for (int j = 0; j < K_NBR; j++)
        o = fmaf(sC[j], sD[j][256 + tid], o);
    out[(size_t)b * H_DIM + tid] = o;
}

// ---------------------------------------------------------------------------
extern "C" void kernel_launch(void* const* d_in, const int* in_sizes, int n_in,
                              void* d_out, int out_size) {
    const int*   neighbors = (const int*)d_in[0];
    const float* embed     = (const float*)d_in[1];
    const float* W1a       = (const float*)d_in[2];
    const float* W1b       = (const float*)d_in[3];
    const float* W2a       = (const float*)d_in[4];
    const float* W2b       = (const float*)d_in[5];
    const float* W3a       = (const float*)d_in[6];
    const float* W3b       = (const float*)d_in[7];
    float* out = (float*)d_out;

    prep_weights_kernel<<<144, 256>>>(W1a, W1b, W2a, W2b, W3a, W3b);

    cudaFuncSetAttribute(precompute_mma_kernel,
                         cudaFuncAttributeMaxDynamicSharedMemorySize,
                         (int)PC_SMEM);
    const int grid1 = (N_NODES + 127) / 128;   // 782
    precompute_mma_kernel<<<grid1, 256, PC_SMEM>>>(embed);

    attention_kernel<<<B_BATCH, 128>>>(neighbors, out);
}

// round 5
// speedup vs baseline: 5.8553x; 1.1490x over previous
#include <cuda_runtime.h>
#include <cuda_fp16.h>
#include <cstdint>
#include <cstddef>

#define N_NODES 100000
#define B_BATCH 20000
#define K_NBR   10
#define F_DIM   256
#define H_DIM   128

// ---------------------------------------------------------------------------
// Device scratch
// ---------------------------------------------------------------------------
__device__ float g_table[(size_t)N_NODES * 384];      // [q|k|v] per node
// Prepacked fp16 B fragments (mma.m16n8k16 register layout), hi/lo split.
// Ba: [p][kstep(16)][term(2)][ntile(16)*32+lane]  (K=256 GEMM1)
// Bb: [p][kstep(8) ][term(2)][ntile(16)*32+lane]  (K=128 GEMM2)
__device__ uint2 g_Ba[3 * 16 * 2 * 512];
__device__ uint2 g_Bb[3 *  8 * 2 * 512];

// ---------------------------------------------------------------------------
// Helpers
// ---------------------------------------------------------------------------
__device__ __forceinline__ uint32_t smem_u32(const void* p) {
    uint32_t a;
    asm("{ .reg .u64 t; cvta.to.shared.u64 t, %1; cvt.u32.u64 %0, t; }"
        : "=r"(a) : "l"(p));
    return a;
}
__device__ __forceinline__ uint32_t pack_f16x2(float a, float b) {
    half2 h = __floats2half2_rn(a, b);
    return *(uint32_t*)&h;
}
__device__ __forceinline__ float f16_round(float x) {
    return __half2float(__float2half_rn(x));
}
__device__ __forceinline__ float tanh_fast(float x) {
    float e = __expf(2.f * x);
    return 1.f - __fdividef(2.f, e + 1.f);
}
__device__ __forceinline__ void ldm4(uint32_t* r, uint32_t addr) {
    asm volatile("ldmatrix.sync.aligned.m8n8.x4.shared.b16 {%0,%1,%2,%3}, [%4];"
                 : "=r"(r[0]), "=r"(r[1]), "=r"(r[2]), "=r"(r[3]) : "r"(addr));
}
__device__ __forceinline__ void mma16816(float* d, const uint32_t* a,
                                         uint32_t b0, uint32_t b1) {
    asm volatile(
        "mma.sync.aligned.m16n8k16.row.col.f32.f16.f16.f32 "
        "{%0,%1,%2,%3}, {%4,%5,%6,%7}, {%8,%9}, {%0,%1,%2,%3};"
        : "+f"(d[0]), "+f"(d[1]), "+f"(d[2]), "+f"(d[3])
        : "r"(a[0]), "r"(a[1]), "r"(a[2]), "r"(a[3]), "r"(b0), "r"(b1));
}

// ---------------------------------------------------------------------------
// Kernel 0: prepack weights into mma B-fragment layout, fp16 hi + lo split.
//   reg.x: k = kstep*16 + (lane%4)*2 + {0,1}, n = ntile*8 + lane/4
//   reg.y: k = ... + 8 + {0,1}
// ---------------------------------------------------------------------------
__global__ void prep_weights_kernel(
    const float* __restrict__ W1a, const float* __restrict__ W1b,
    const float* __restrict__ W2a, const float* __restrict__ W2b,
    const float* __restrict__ W3a, const float* __restrict__ W3b)
{
    const float* Wa[3] = {W1a, W2a, W3a};
    const float* Wb[3] = {W1b, W2b, W3b};
    int i = blockIdx.x * blockDim.x + threadIdx.x;   // 36864 threads
    const float* W;
    uint2 *dst_hi, *dst_lo;
    int lane, nt, ks;
    if (i < 24576) {                                 // Ba: 3*16*16*32
        lane = i & 31; nt = (i >> 5) & 15; ks = (i >> 9) & 15;
        int p = i >> 13;
        W = Wa[p];
        size_t base = (size_t)((p * 16 + ks) * 2) * 512 + nt * 32 + lane;
        dst_hi = g_Ba + base;
        dst_lo = g_Ba + base + 512;
    } else {                                         // Bb: 3*8*16*32
        int ib = i - 24576;
        lane = ib & 31; nt = (ib >> 5) & 15; ks = (ib >> 9) & 7;
        int p = ib >> 12;
        W = Wb[p];
        size_t base = (size_t)((p * 8 + ks) * 2) * 512 + nt * 32 + lane;
        dst_hi = g_Bb + base;
        dst_lo = g_Bb + base + 512;
    }
    int k = ks * 16 + (lane & 3) * 2;
    int n = nt * 8 + (lane >> 2);
    float w00 = W[(size_t)k * H_DIM + n];
    float w01 = W[(size_t)(k + 1) * H_DIM + n];
    float w10 = W[(size_t)(k + 8) * H_DIM + n];
    float w11 = W[(size_t)(k + 9) * H_DIM + n];
    float h00 = f16_round(w00), h01 = f16_round(w01);
    float h10 = f16_round(w10), h11 = f16_round(w11);
    uint2 hi, lo;
    hi.x = pack_f16x2(h00, h01);
    hi.y = pack_f16x2(h10, h11);
    lo.x = pack_f16x2(w00 - h00, w01 - h01);
    lo.y = pack_f16x2(w10 - h10, w11 - h11);
    *dst_hi = hi;
    *dst_lo = lo;
}

// ---------------------------------------------------------------------------
// Kernel 1: HMMA precompute. CTA = 128x128 tile, 8 warps as 2m x 4n,
// warp tile 64x32. Split-2 on B: D = A16 * (Bh + Bl), fp32 accum.
// smem: X fp16 [128][264] + H fp16 [128][136] = 102.4 KB -> 2 CTAs/SM.
// ---------------------------------------------------------------------------
#define XSTR 264
#define HSTR 136
#define X_OFF 0u
#define H_OFF 67584u                     // 128*264*2
#define PC_SMEM 102400u                  // + 128*136*2 = 34816

__global__ void __launch_bounds__(256, 2) precompute_mma_kernel(
    const float* __restrict__ embed)
{
    extern __shared__ unsigned char smem[];
    const uint32_t sbase = smem_u32(smem);
    const int tid  = threadIdx.x;
    const int wid  = tid >> 5;
    const int lane = tid & 31;
    const int wm   = wid & 1;            // m-group: rows wm*64..+63
    const int wn   = wid >> 1;           // n-group: cols wn*32..+31
    const long brow = (long)blockIdx.x * 128;

    const uint32_t loffX = (uint32_t)((lane & 15) * XSTR + (lane >> 4) * 8) * 2;
    const uint32_t loffH = (uint32_t)((lane & 15) * HSTR + (lane >> 4) * 8) * 2;

    // ---- Load X tile [128][256] fp32 -> fp16 smem ----
    for (int i = tid; i < 128 * 64; i += 256) {
        int r  = i >> 6;
        int c4 = i & 63;
        long grow = brow + r;
        float4 v = make_float4(0.f, 0.f, 0.f, 0.f);
        if (grow < N_NODES) v = *(const float4*)(embed + grow * F_DIM + c4 * 4);
        uint32_t off = ((uint32_t)r * XSTR + c4 * 4) * 2;
        *(uint32_t*)(smem + X_OFF + off)     = pack_f16x2(v.x, v.y);
        *(uint32_t*)(smem + X_OFF + off + 4) = pack_f16x2(v.z, v.w);
    }
    __syncthreads();

    const int rbase = (lane >> 2);
    const int cbase = (lane & 3) * 2;

    for (int p = 0; p < 3; p++) {
        float acc[4][4][4];
        #pragma unroll
        for (int mt = 0; mt < 4; mt++)
            #pragma unroll
            for (int nt = 0; nt < 4; nt++)
                #pragma unroll
                for (int c = 0; c < 4; c++) acc[mt][nt][c] = 0.f;

        // ================= GEMM1: X[128,256] @ Wa -> 128x128 =================
        for (int ks = 0; ks < 16; ks++) {
            uint32_t a[4][4];
            uint32_t kb = (uint32_t)ks * 32;
            #pragma unroll
            for (int mt = 0; mt < 4; mt++) {
                uint32_t ro = (uint32_t)(wm * 64 + mt * 16) * XSTR * 2;
                ldm4(a[mt], sbase + X_OFF + ro + kb + loffX);
            }
            const uint2* pb = g_Ba + (size_t)((p * 16 + ks) * 2) * 512
                              + (wn * 4) * 32 + lane;
            uint2 bh[4], bl[4];
            #pragma unroll
            for (int j = 0; j < 4; j++) { bh[j] = pb[j * 32]; bl[j] = pb[512 + j * 32]; }
            #pragma unroll
            for (int j = 0; j < 4; j++) {
                #pragma unroll
                for (int mt = 0; mt < 4; mt++) {
                    mma16816(acc[mt][j], a[mt], bh[j].x, bh[j].y);
                    mma16816(acc[mt][j], a[mt], bl[j].x, bl[j].y);
                }
            }
        }

        // ---- Epilogue 1: tanh -> H smem (fp16) ----
        #pragma unroll
        for (int mt = 0; mt < 4; mt++) {
            #pragma unroll
            for (int nt = 0; nt < 4; nt++) {
                int col = wn * 32 + nt * 8 + cbase;
                int r0  = wm * 64 + mt * 16 + rbase;
                float t0 = tanh_fast(acc[mt][nt][0]);
                float t1 = tanh_fast(acc[mt][nt][1]);
                float t2 = tanh_fast(acc[mt][nt][2]);
                float t3 = tanh_fast(acc[mt][nt][3]);
                uint32_t o0 = ((uint32_t)r0 * HSTR + col) * 2;
                uint32_t o1 = ((uint32_t)(r0 + 8) * HSTR + col) * 2;
                *(uint32_t*)(smem + H_OFF + o0) = pack_f16x2(t0, t1);
                *(uint32_t*)(smem + H_OFF + o1) = pack_f16x2(t2, t3);
            }
        }
        __syncthreads();

        // ================= GEMM2: H[128,128] @ Wb -> 128x128 =================
        #pragma unroll
        for (int mt = 0; mt < 4; mt++)
            #pragma unroll
            for (int nt = 0; nt < 4; nt++)
                #pragma unroll
                for (int c = 0; c < 4; c++) acc[mt][nt][c] = 0.f;

        for (int ks = 0; ks < 8; ks++) {
            uint32_t a[4][4];
            uint32_t kb = (uint32_t)ks * 32;
            #pragma unroll
            for (int mt = 0; mt < 4; mt++) {
                uint32_t ro = (uint32_t)(wm * 64 + mt * 16) * HSTR * 2;
                ldm4(a[mt], sbase + H_OFF + ro + kb + loffH);
            }
            const uint2* pb = g_Bb + (size_t)((p * 8 + ks) * 2) * 512
                              + (wn * 4) * 32 + lane;
            uint2 bh[4], bl[4];
            #pragma unroll
            for (int j = 0; j < 4; j++) { bh[j] = pb[j * 32]; bl[j] = pb[512 + j * 32]; }
            #pragma unroll
            for (int j = 0; j < 4; j++) {
                #pragma unroll
                for (int mt = 0; mt < 4; mt++) {
                    mma16816(acc[mt][j], a[mt], bh[j].x, bh[j].y);
                    mma16816(acc[mt][j], a[mt], bl[j].x, bl[j].y);
                }
            }
        }

        // ---- Epilogue 2: write to g_table ----
        #pragma unroll
        for (int mt = 0; mt < 4; mt++) {
            #pragma unroll
            for (int nt = 0; nt < 4; nt++) {
                int col = wn * 32 + nt * 8 + cbase;
                long r0 = brow + wm * 64 + mt * 16 + rbase;
                if (r0 < N_NODES) {
                    float2 v = make_float2(acc[mt][nt][0], acc[mt][nt][1]);
                    *(float2*)(g_table + r0 * 384 + p * H_DIM + col) = v;
                }
                if (r0 + 8 < N_NODES) {
                    float2 v = make_float2(acc[mt][nt][2], acc[mt][nt][3]);
                    *(float2*)(g_table + (r0 + 8) * 384 + p * H_DIM + col) = v;
                }
            }
        }
        __syncthreads();   // protect H smem before next projection rewrites it
    }
}

// ---------------------------------------------------------------------------
// Kernel 2: gather + tiny attention (unchanged from round 4).
// ---------------------------------------------------------------------------
#define DSTR 396

template<int G>
__device__ __forceinline__ void score_warp25(const float (*sD)[DSTR],
                                             float* sS, int lane) {
    float4 kv[K_NBR];
    #pragma unroll
    for (int j = 0; j < K_NBR; j++)
        kv[j] = *(const float4*)(&sD[j][128 + 4 * lane]);
    float4 qv = make_float4(0.f, 0.f, 0.f, 0.f);
    #pragma unroll
    for (int p = 0; p < 25; p++) {
        const int gp = G * 25 + p;
        const int i  = gp / K_NBR;
        const int j  = gp % K_NBR;
        if (p == 0 || (gp % K_NBR) == 0)
            qv = *(const float4*)(&sD[i][4 * lane]);
        float s = qv.x * kv[j].x;
        s = fmaf(qv.y, kv[j].y, s);
        s = fmaf(qv.z, kv[j].z, s);
        s = fmaf(qv.w, kv[j].w, s);
        s += __shfl_xor_sync(0xffffffffu, s, 16);
        s += __shfl_xor_sync(0xffffffffu, s, 8);
        s += __shfl_xor_sync(0xffffffffu, s, 4);
        s += __shfl_xor_sync(0xffffffffu, s, 2);
        s += __shfl_xor_sync(0xffffffffu, s, 1);
        if (lane == 0) sS[gp] = s;
    }
}

__global__ void __launch_bounds__(128) attention_kernel(
    const int* __restrict__ neighbors, float* __restrict__ out)
{
    __shared__ float sD[K_NBR][DSTR];
    __shared__ float sS[100];
    __shared__ float sR[K_NBR];
    __shared__ float sC[K_NBR];
    __shared__ int   snode[K_NBR];

    const int b    = blockIdx.x;
    const int tid  = threadIdx.x;
    const int lane = tid & 31;
    const int g    = tid >> 5;

    if (tid < K_NBR) snode[tid] = neighbors[(size_t)b * K_NBR + tid];
    __syncthreads();

    for (int i = tid; i < K_NBR * 96; i += 128) {
        int j  = i / 96;
        int c4 = i - j * 96;
        float4 v = *(const float4*)(g_table + (size_t)snode[j] * 384 + c4 * 4);
        *(float4*)(&sD[j][c4 * 4]) = v;
    }
    __syncthreads();

    switch (g) {
        case 0: score_warp25<0>(sD, sS, lane); break;
        case 1: score_warp25<1>(sD, sS, lane); break;
        case 2: score_warp25<2>(sD, sS, lane); break;
        default: score_warp25<3>(sD, sS, lane); break;
    }
    __syncthreads();

    if (tid < K_NBR) {
        float m = -1e30f;
        #pragma unroll
        for (int j = 0; j < K_NBR; j++) m = fmaxf(m, sS[tid * K_NBR + j]);
        float sum = 0.f;
        #pragma unroll
        for (int j = 0; j < K_NBR; j++) {
            float e = __expf(sS[tid * K_NBR + j] - m);
            sS[tid * K_NBR + j] = e;
            sum += e;
        }
        sR[tid] = sum;
    }
    __syncthreads();

    if (tid < K_NBR) {
        float cw = 0.f;
        #pragma unroll
        for (int i = 0; i < K_NBR; i++)
            cw += sS[i * K_NBR + tid] / sR[i];
        sC[tid] = cw;
    }
    __syncthreads();

    float o = 0.f;
    #pragma unroll
    for (int j = 0; j < K_NBR; j++)
        o = fmaf(sC[j], sD[j][256 + tid], o);
    out[(size_t)b * H_DIM + tid] = o;
}

// ---------------------------------------------------------------------------
extern "C" void kernel_launch(void* const* d_in, const int* in_sizes, int n_in,
                              void* d_out, int out_size) {
    const int*   neighbors = (const int*)d_in[0];
    const float* embed     = (const float*)d_in[1];
    const float* W1a       = (const float*)d_in[2];
    const float* W1b       = (const float*)d_in[3];
    const float* W2a       = (const float*)d_in[4];
    const float* W2b       = (const float*)d_in[5];
    const float* W3a       = (const float*)d_in[6];
    const float* W3b       = (const float*)d_in[7];
    float* out = (float*)d_out;

    prep_weights_kernel<<<144, 256>>>(W1a, W1b, W2a, W2b, W3a, W3b);

    cudaFuncSetAttribute(precompute_mma_kernel,
                         cudaFuncAttributeMaxDynamicSharedMemorySize,
                         (int)PC_SMEM);
    const int grid1 = (N_NODES + 127) / 128;   // 782
    precompute_mma_kernel<<<grid1, 256, PC_SMEM>>>(embed);

    attention_kernel<<<B_BATCH, 128>>>(neighbors, out);
}